// round 17
// baseline (speedup 1.0000x reference)
#include <cuda_runtime.h>
#include <cuda_bf16.h>
#include <cuda_fp16.h>
#include <cstdint>
#include <math.h>

#define L_   2048
#define E_   1024
#define H_   16
#define D_   64
#define MBL_ 2048

// ---------------- device scratch (static; allocation-free) -----------------
// e in PV-fragment layout: [h][iq(32)][chunk(16)][slot(32)][wm(4)*32+lane] u32
__device__ uint32_t g_ef[(size_t)H_ * 32 * 16 * 4096];

// fp16 operands for the big GEMMs
__device__ __half g_xh[L_ * E_];
__device__ __half g_wh[4 * E_ * E_], g_wl[4 * E_ * E_];   // lo used for Wo only
__device__ __half g_aoh[L_ * E_];
// fp16 attention operands, [H][L][64] (all single-rounded)
__device__ __half g_qh[H_ * L_ * D_];
__device__ __half g_kh[H_ * L_ * D_];
__device__ __half g_vh[H_ * L_ * D_];

// ============================ PTX helpers (sm_80+) ==========================
__device__ __forceinline__ uint32_t smem_u32(const void* p) {
    uint32_t a;
    asm("{ .reg .u64 t; cvta.to.shared.u64 t, %1; cvt.u32.u64 %0, t; }"
        : "=r"(a) : "l"(p));
    return a;
}
__device__ __forceinline__ void cp16(uint32_t dst, const void* src) {
    asm volatile("cp.async.cg.shared.global [%0], [%1], 16;" :: "r"(dst), "l"(src));
}
#define CP_COMMIT()  asm volatile("cp.async.commit_group;" ::: "memory")
#define CP_WAIT(n)   asm volatile("cp.async.wait_group %0;" :: "n"(n) : "memory")

__device__ __forceinline__ void ldsm4(uint32_t a[4], uint32_t addr) {
    asm volatile("ldmatrix.sync.aligned.m8n8.x4.shared.b16 {%0,%1,%2,%3}, [%4];"
        : "=r"(a[0]), "=r"(a[1]), "=r"(a[2]), "=r"(a[3]) : "r"(addr));
}
__device__ __forceinline__ void ldsm2(uint32_t a[2], uint32_t addr) {
    asm volatile("ldmatrix.sync.aligned.m8n8.x2.shared.b16 {%0,%1}, [%2];"
        : "=r"(a[0]), "=r"(a[1]) : "r"(addr));
}
__device__ __forceinline__ void ldsm2t(uint32_t a[2], uint32_t addr) {
    asm volatile("ldmatrix.sync.aligned.m8n8.x2.trans.shared.b16 {%0,%1}, [%2];"
        : "=r"(a[0]), "=r"(a[1]) : "r"(addr));
}
__device__ __forceinline__ void mma_fp(float d[4], const uint32_t a[4], const uint32_t b[2]) {
    asm volatile("mma.sync.aligned.m16n8k16.row.col.f32.f16.f16.f32 "
        "{%0,%1,%2,%3}, {%4,%5,%6,%7}, {%8,%9}, {%0,%1,%2,%3};"
        : "+f"(d[0]), "+f"(d[1]), "+f"(d[2]), "+f"(d[3])
        : "r"(a[0]), "r"(a[1]), "r"(a[2]), "r"(a[3]), "r"(b[0]), "r"(b[1]));
}

// fast exp on FMA pipe (no MUFU)
__device__ __forceinline__ float fexp(float x) {
    float z  = fmaxf(x, -80.f) * 1.4426950408889634f;
    float fz = z + 12582912.f;
    int   n  = __float_as_int(fz) - 0x4B400000;
    float f  = z - (float)n;
    float p  = 1.3333558146428443e-3f;
    p = fmaf(p, f, 9.6181291076284772e-3f);
    p = fmaf(p, f, 5.5504108664821580e-2f);
    p = fmaf(p, f, 2.4022650695910071e-1f);
    p = fmaf(p, f, 6.9314718055994531e-1f);
    p = fmaf(p, f, 1.0f);
    return p * __int_as_float((n + 127) << 23);
}

// relu(e * iz + tt) on a packed half2, returned packed
__device__ __forceinline__ uint32_t trelu2(uint32_t e, float iz, float tt) {
    float2 f = __half22float2(*(__half2*)&e);
    float t0 = fmaxf(fmaf(f.x, iz, tt), 0.f);
    float t1 = fmaxf(fmaf(f.y, iz, tt), 0.f);
    __half2 r = __floats2half2_rn(t0, t1);
    return *(uint32_t*)&r;
}

// ============================================================================
// fp32 -> fp16 conversions, one launch.
// ============================================================================
__global__ __launch_bounds__(256) void conv_all(
    const float* __restrict__ x,  const float* __restrict__ Wq,
    const float* __restrict__ Wk, const float* __restrict__ Wv,
    const float* __restrict__ Wo)
{
    int b = blockIdx.x;
    if (b < 2048) {
        int i = b * 256 + threadIdx.x;
        float4 v = ((const float4*)x)[i];
        __half2* hp = (__half2*)(g_xh + i * 4);
        hp[0] = __floats2half2_rn(v.x, v.y);
        hp[1] = __floats2half2_rn(v.z, v.w);
        return;
    }
    int wsel = (b - 2048) >> 10;
    int off  = (b - 2048) & 1023;
    const float* s = (wsel == 0) ? Wq : (wsel == 1) ? Wk : (wsel == 2) ? Wv : Wo;
    __half* hi = g_wh + (size_t)wsel * (E_ * E_);
    int i = off * 256 + threadIdx.x;
    float4 v = ((const float4*)s)[i];
    __half h0 = __float2half_rn(v.x), h1 = __float2half_rn(v.y);
    __half h2 = __float2half_rn(v.z), h3 = __float2half_rn(v.w);
    __half2* hp = (__half2*)(hi + i * 4);
    hp[0] = __halves2half2(h0, h1); hp[1] = __halves2half2(h2, h3);
    if (wsel == 3) {                  // only Wo keeps a lo correction
        __half l0 = __float2half_rn(v.x - __half2float(h0));
        __half l1 = __float2half_rn(v.y - __half2float(h1));
        __half l2 = __float2half_rn(v.z - __half2float(h2));
        __half l3 = __float2half_rn(v.w - __half2float(h3));
        __half2* lp = (__half2*)(g_wl + (size_t)wsel * (E_ * E_) + i * 4);
        lp[0] = __halves2half2(l0, l1); lp[1] = __halves2half2(l2, l3);
    }
}

// ============================================================================
// fp16 GEMM on mma.sync: C[128,128] = A[M,K] * B[N,K]^T  (frozen)
// ============================================================================
#define BK    64
#define NCHK  (E_ / BK)
#define TILEB (128 * BK * 2)
#define SMEM_MMA1 (2 * 2 * TILEB)
#define SMEM_MMA2 (2 * 3 * TILEB)

__device__ __forceinline__ void load_tile_async(
    uint32_t dst, const __half* src, int row0, int kt, int tid)
{
#pragma unroll
    for (int it = 0; it < 4; it++) {
        int c = tid + it * 256;
        int row = c >> 3;
        int ch  = c & 7;
        const __half* sp = src + (size_t)(row0 + row) * E_ + kt + ch * 8;
        uint32_t sw = row * 128 + ((ch ^ (row & 7)) << 4);
        cp16(dst + sw, sp);
    }
}

__global__ void __launch_bounds__(256, 2) mma_gemm(int mode, float* __restrict__ out)
{
    extern __shared__ char smem[];
    uint32_t sbase = smem_u32(smem);
    int tid  = threadIdx.x;
    int lane = tid & 31;
    int w    = tid >> 5;
    int wm   = w >> 2;
    int wn   = w & 3;
    int z    = blockIdx.z;
    int m0   = blockIdx.y * 128;
    int n0   = blockIdx.x * 128;

    const __half* A = (mode == 0) ? g_xh : g_aoh;
    int wsel = (mode == 0) ? z : 3;
    const __half* Bhi = g_wh + (size_t)wsel * (E_ * E_);
    const __half* Blo = g_wl + (size_t)wsel * (E_ * E_);
    int nt = (mode == 0) ? 1 : 2;
    uint32_t stageb = (nt == 1) ? (2 * TILEB) : (3 * TILEB);

    float acc[4][4][4];
#pragma unroll
    for (int mi = 0; mi < 4; mi++)
#pragma unroll
        for (int ni = 0; ni < 4; ni++)
#pragma unroll
            for (int r = 0; r < 4; r++) acc[mi][ni][r] = 0.f;

    int rl = lane & 7;
    int ai = lane >> 3;
    int aci = ai >> 1;
    int arow[4];
#pragma unroll
    for (int mi = 0; mi < 4; mi++)
        arow[mi] = (wm * 64 + mi * 16 + (ai & 1) * 8 + rl) * 128;
    int bi = (lane >> 3) & 1;
    int brow[4];
#pragma unroll
    for (int ni = 0; ni < 4; ni++)
        brow[ni] = (wn * 32 + ni * 8 + rl) * 128;

    load_tile_async(sbase + 0 * TILEB, A,   m0, 0, tid);
    load_tile_async(sbase + 1 * TILEB, Bhi, n0, 0, tid);
    if (nt == 2) load_tile_async(sbase + 2 * TILEB, Blo, n0, 0, tid);
    CP_COMMIT();

    for (int kt = 0; kt < NCHK; kt++) {
        bool more = (kt + 1) < NCHK;
        if (more) {
            uint32_t nb = sbase + ((kt + 1) & 1) * stageb;
            int kk = (kt + 1) * BK;
            load_tile_async(nb + 0 * TILEB, A,   m0, kk, tid);
            load_tile_async(nb + 1 * TILEB, Bhi, n0, kk, tid);
            if (nt == 2) load_tile_async(nb + 2 * TILEB, Blo, n0, kk, tid);
            CP_COMMIT();
            CP_WAIT(1);
        } else {
            CP_WAIT(0);
        }
        __syncthreads();

        uint32_t st = sbase + (kt & 1) * stageb;
#pragma unroll
        for (int ks = 0; ks < 4; ks++) {
            uint32_t af[4][4];
            uint32_t choA = (((ks * 2 + aci) ^ rl) << 4);
            uint32_t choB = (((ks * 2 + bi) ^ rl) << 4);
#pragma unroll
            for (int mi = 0; mi < 4; mi++)
                ldsm4(af[mi], st + arow[mi] + choA);
            for (int t = 0; t < nt; t++) {
                uint32_t uB = st + TILEB + t * TILEB;
                uint32_t bf[4][2];
#pragma unroll
                for (int ni = 0; ni < 4; ni++)
                    ldsm2(bf[ni], uB + brow[ni] + choB);
#pragma unroll
                for (int mi = 0; mi < 4; mi++)
#pragma unroll
                    for (int ni = 0; ni < 4; ni++)
                        mma_fp(acc[mi][ni], af[mi], bf[ni]);
            }
        }
        __syncthreads();
    }

    int mrow = m0 + wm * 64 + (lane >> 2);
    int ncol = n0 + wn * 32 + (lane & 3) * 2;
#pragma unroll
    for (int mi = 0; mi < 4; mi++) {
#pragma unroll
        for (int ni = 0; ni < 4; ni++) {
            int n = ncol + ni * 8;
#pragma unroll
            for (int half = 0; half < 2; half++) {
                int m = mrow + mi * 16 + half * 8;
                float v0 = acc[mi][ni][half * 2], v1 = acc[mi][ni][half * 2 + 1];
                if (mode == 0) {
                    size_t o = ((size_t)(n >> 6) * L_ + m) * 64 + (n & 63);
                    __half* C = (z == 0) ? g_qh : (z == 1) ? g_kh : g_vh;
                    *(__half2*)(C + o) = __floats2half2_rn(v0, v1);
                } else {
                    *(float2*)(out + (size_t)m * E_ + n) = make_float2(v0, v1);
                }
            }
        }
    }
}

// ============================================================================
// Attention. Grid 512 = 32 q-tiles (heavy first) x 16 heads; 64-row q-tiles.
// 256 thr = 8 warps: 4 m-warps x 2 n-warps. BK=128 k-chunks. 3 CTAs/SM.
// 3-stage KV ring + always-commit groups => ONE __syncthreads per chunk.
// Pass 1: S = q*k mma, e -> g_ef in PV-fragment layout. Pass 2: T in regs
// from g_ef, O += T*V (V via ldsm2t), O -> g_aoh fp16.
// ============================================================================
#define AQ_    0u          /* 8 KB: Q (pass1 only) */
#define AKV_   8192u       /* 3 bufs x 16 KB (K in pass1, V in pass2) */
#define ABIAS_ 57344u      /* 8 KB */
#define AZP_   65536u      /* 2 x 64 floats */
#define AINVZ_ 66048u
#define ATAUT_ 66304u
#define SMEM_ATT 66560

__global__ void __launch_bounds__(256, 3) attn_kernel(
    const float* __restrict__ bias, const float* __restrict__ tau)
{
    extern __shared__ char smem[];
    uint32_t sb = smem_u32(smem);
    float* sbias = (float*)(smem + ABIAS_);
    float* szp   = (float*)(smem + AZP_);
    float* sinvz = (float*)(smem + AINVZ_);
    float* staut = (float*)(smem + ATAUT_);

    int bx  = blockIdx.x;
    int iq  = 31 - (bx >> 4);       // heavy q-tiles first
    int h   = bx & 15;
    int q0  = iq * 64;
    int nch = (q0 + 64 + 127) >> 7; // 128-row k-chunks covering [0, q0+64)

    int tid = threadIdx.x;
    int lane = tid & 31, w = tid >> 5;
    int wm = w >> 1, wn = w & 1;    // 4 m-warps x 2 n-warps
    int rl = lane & 7;
    int ai = lane >> 3, aci = ai >> 1, bi = ai & 1;
    float tauh = tau[h];
    const float scale = 0.125f;

    for (int i = tid; i < MBL_ / 4; i += 256)
        *(float4*)&sbias[i * 4] = *(const float4*)&bias[h * MBL_ + i * 4];

    const __half* qh = g_qh + (size_t)h * (L_ * 64);
    const __half* kh = g_kh + (size_t)h * (L_ * 64);
    const __half* vh = g_vh + (size_t)h * (L_ * 64);
    uint32_t* efb = g_ef + (size_t)(h * 32 + iq) * (16 * 4096);

    uint32_t arow = (uint32_t)((wm * 16 + (ai & 1) * 8 + rl) * 128);
    uint32_t brow8[8];
#pragma unroll
    for (int ni = 0; ni < 8; ni++)
        brow8[ni] = (uint32_t)((wn * 64 + ni * 8 + rl) * 128);

    // ---- prologue: Q + K0 (group 0), K1/empty (group 1) ----
#pragma unroll
    for (int it = 0; it < 2; it++) {
        int c = tid + it * 256;
        int row = c >> 3, ch = c & 7;
        uint32_t sw = row * 128 + ((ch ^ (row & 7)) << 4);
        cp16(sb + AQ_ + sw, qh + (size_t)(q0 + row) * 64 + ch * 8);
    }
#pragma unroll
    for (int it = 0; it < 4; it++) {
        int c = tid + it * 256;
        int row = c >> 3, ch = c & 7;
        uint32_t sw = row * 128 + ((ch ^ (row & 7)) << 4);
        cp16(sb + AKV_ + sw, kh + (size_t)row * 64 + ch * 8);
    }
    CP_COMMIT();
    if (nch > 1) {
#pragma unroll
        for (int it = 0; it < 4; it++) {
            int c = tid + it * 256;
            int row = c >> 3, ch = c & 7;
            uint32_t sw = row * 128 + ((ch ^ (row & 7)) << 4);
            cp16(sb + AKV_ + 16384 + sw, kh + (size_t)(128 + row) * 64 + ch * 8);
        }
    }
    CP_COMMIT();

    float rs[2] = {0.f, 0.f};

    // ==================== PASS 1 (one sync per chunk) ====================
    for (int j = 0; j < nch; j++) {
        CP_WAIT(1);                 // chunk j's group retired
        __syncthreads();            // data visible; prev-iter consumes done

        int k0 = j * 128;
        float sacc[8][4];
#pragma unroll
        for (int ni = 0; ni < 8; ni++)
#pragma unroll
            for (int r = 0; r < 4; r++) sacc[ni][r] = 0.f;

        uint32_t bkh = sb + AKV_ + (uint32_t)(j % 3) * 16384;
#pragma unroll
        for (int ks = 0; ks < 4; ks++) {
            uint32_t qf[4];
            uint32_t choA = (((ks * 2 + aci) ^ rl) << 4);
            uint32_t choB = (((ks * 2 + bi) ^ rl) << 4);
            ldsm4(qf, sb + AQ_ + arow + choA);
#pragma unroll
            for (int ni = 0; ni < 8; ni++) {
                uint32_t kf[2];
                ldsm2(kf, bkh + brow8[ni] + choB);
                mma_fp(sacc[ni], qf, kf);
            }
        }

        // prefetch K_{j+2} into ring slot (safe: slot last read in iter j-1)
        if (j + 2 < nch) {
            uint32_t nb = sb + AKV_ + (uint32_t)((j + 2) % 3) * 16384;
            int k0n = (j + 2) * 128;
#pragma unroll
            for (int it = 0; it < 4; it++) {
                int c = tid + it * 256;
                int row = c >> 3, ch = c & 7;
                uint32_t sw = row * 128 + ((ch ^ (row & 7)) << 4);
                cp16(nb + sw, kh + (size_t)(k0n + row) * 64 + ch * 8);
            }
        }
        CP_COMMIT();                // always (possibly empty) to keep counts

        // epilogue: scale + bias + causal, exp, store e (fragment layout), Z
        int r = wm * 16 + (lane >> 2);
        uint32_t* efj = efb + j * 4096 + wm * 32 + lane;
#pragma unroll
        for (int ni = 0; ni < 8; ni++) {
            int kk = k0 + wn * 64 + ni * 8 + (lane & 3) * 2;
            int slot = wn * 4 + (ni >> 1);
#pragma unroll
            for (int hh = 0; hh < 2; hh++) {
                int qq = q0 + r + hh * 8;
                float s0 = sacc[ni][hh * 2]     * scale;
                float s1 = sacc[ni][hh * 2 + 1] * scale;
                int d0 = qq - kk, d1 = d0 - 1;
                float e0 = (d0 >= 0) ? fexp(s0 + sbias[d0]) : 0.f;
                float e1 = (d1 >= 0) ? fexp(s1 + sbias[d1]) : 0.f;
                __half2 ep = __floats2half2_rn(e0, e1);
                efj[(slot * 4 + (ni & 1) * 2 + hh) * 128] = *(uint32_t*)&ep;
                rs[hh] += e0 + e1;
            }
        }
    }
    CP_WAIT(0);                     // flush leftover (empty) groups

    // ---- finalize Z ----
#pragma unroll
    for (int hh = 0; hh < 2; hh++) {
        rs[hh] += __shfl_xor_sync(0xffffffffu, rs[hh], 1);
        rs[hh] += __shfl_xor_sync(0xffffffffu, rs[hh], 2);
    }
    if ((lane & 3) == 0) {
        int r0 = wm * 16 + (lane >> 2);
        szp[wn * 64 + r0]     = rs[0];
        szp[wn * 64 + r0 + 8] = rs[1];
    }
    __syncthreads();                // szp ready; all pass-1 smem reads done
    if (tid < 64) {
        float Zr = szp[tid] + szp[64 + tid];
        sinvz[tid] = 1.f / Zr;
        staut[tid] = tauh / (float)(q0 + tid + 1);
    }
    // ---- V prologue: V0 (group), V1/empty (group) ----
#pragma unroll
    for (int it = 0; it < 4; it++) {
        int c = tid + it * 256;
        int row = c >> 3, ch = c & 7;
        uint32_t sw = row * 128 + ((ch ^ (row & 7)) << 4);
        cp16(sb + AKV_ + sw, vh + (size_t)row * 64 + ch * 8);
    }
    CP_COMMIT();
    if (nch > 1) {
#pragma unroll
        for (int it = 0; it < 4; it++) {
            int c = tid + it * 256;
            int row = c >> 3, ch = c & 7;
            uint32_t sw = row * 128 + ((ch ^ (row & 7)) << 4);
            cp16(sb + AKV_ + 16384 + sw, vh + (size_t)(128 + row) * 64 + ch * 8);
        }
    }
    CP_COMMIT();
    __syncthreads();                // sinvz/staut visible to all

    // per-thread row constants for pass 2
    int rr = wm * 16 + (lane >> 2);
    float iz0 = sinvz[rr],     tt0 = staut[rr];
    float iz1 = sinvz[rr + 8], tt1 = staut[rr + 8];
    const uint32_t* efr = efb + wm * 32 + lane;

    // ==================== PASS 2 (one sync per chunk) ====================
    float oacc[4][4];
#pragma unroll
    for (int ni = 0; ni < 4; ni++)
#pragma unroll
        for (int r = 0; r < 4; r++) oacc[ni][r] = 0.f;

    for (int j = 0; j < nch; j++) {
        CP_WAIT(1);
        __syncthreads();

        const uint32_t* efc = efr + j * 4096;
        uint32_t bv = sb + AKV_ + (uint32_t)(j % 3) * 16384;
        int krl = lane & 15;
#pragma unroll
        for (int ks = 0; ks < 8; ks++) {
            uint32_t tf[4], vf[4][2];
            tf[0] = trelu2(efc[(ks * 4 + 0) * 128], iz0, tt0);
            tf[1] = trelu2(efc[(ks * 4 + 1) * 128], iz1, tt1);
            tf[2] = trelu2(efc[(ks * 4 + 2) * 128], iz0, tt0);
            tf[3] = trelu2(efc[(ks * 4 + 3) * 128], iz1, tt1);
            int kr = ks * 16 + krl;              // 0..127 V rows
#pragma unroll
            for (int ni = 0; ni < 4; ni++) {
                uint32_t off = kr * 128 + (((wn * 4 + ni) ^ (kr & 7)) << 4);
                ldsm2t(vf[ni], bv + off);
            }
#pragma unroll
            for (int ni = 0; ni < 4; ni++)
                mma_fp(oacc[ni], tf, vf[ni]);
        }

        if (j + 2 < nch) {
            uint32_t nb = sb + AKV_ + (uint32_t)((j + 2) % 3) * 16384;
            int k0n = (j + 2) * 128;
#pragma unroll
            for (int it = 0; it < 4; it++) {
                int c = tid + it * 256;
                int row = c >> 3, ch = c & 7;
                uint32_t sw = row * 128 + ((ch ^ (row & 7)) << 4);
                cp16(nb + sw, vh + (size_t)(k0n + row) * 64 + ch * 8);
            }
        }
        CP_COMMIT();
    }
    CP_WAIT(0);

    // ---- O -> g_aoh fp16 ----
#pragma unroll
    for (int ni = 0; ni < 4; ni++) {
        int c = wn * 32 + ni * 8 + (lane & 3) * 2;
#pragma unroll
        for (int hh = 0; hh < 2; hh++) {
            int q = q0 + wm * 16 + (lane >> 2) + hh * 8;
            float v0 = oacc[ni][hh * 2], v1 = oacc[ni][hh * 2 + 1];
            size_t o = (size_t)q * E_ + h * 64 + c;
            *(__half2*)(g_aoh + o) = __floats2half2_rn(v0, v1);
        }
    }
}

// ============================================================================
extern "C" void kernel_launch(void* const* d_in, const int* in_sizes, int n_in,
                              void* d_out, int out_size)
{
    (void)in_sizes; (void)n_in; (void)out_size;
    const float* x    = (const float*)d_in[0];
    const float* Wq   = (const float*)d_in[1];
    const float* Wk   = (const float*)d_in[2];
    const float* Wv   = (const float*)d_in[3];
    const float* Wo   = (const float*)d_in[4];
    const float* bias = (const float*)d_in[5];
    const float* tau  = (const float*)d_in[6];
    float* out = (float*)d_out;

    cudaFuncSetAttribute(mma_gemm, cudaFuncAttributeMaxDynamicSharedMemorySize, SMEM_MMA2);
    cudaFuncSetAttribute(attn_kernel, cudaFuncAttributeMaxDynamicSharedMemorySize, SMEM_ATT);

    conv_all<<<2048 + 4 * 1024, 256>>>(x, Wq, Wk, Wv, Wo);
    mma_gemm<<<dim3(E_ / 128, L_ / 128, 3), 256, SMEM_MMA1>>>(0, nullptr);
    attn_kernel<<<512, 256, SMEM_ATT>>>(bias, tau);
    mma_gemm<<<dim3(E_ / 128, L_ / 128, 1), 256, SMEM_MMA2>>>(1, out);
}